// round 16
// baseline (speedup 1.0000x reference)
#include <cuda_runtime.h>
#include <cuda_fp16.h>
#include <math.h>

// Problem dims (fixed)
#define B_      8
#define H_      32
#define TQ_     8
#define KV_     4096
#define D_      128

// Split-KV config
#define NSPLIT_ 8
#define KVS_    (KV_ / NSPLIT_)   // 512 rows per split
#define TS_     32                // KV rows per tile
#define NTILES_ (KVS_ / TS_)      // 16
#define NPART_  (B_ * H_ * NSPLIT_) // 2048

typedef unsigned long long u64;

// Scratch for split partials (device globals: allocation-free)
__device__ float g_po[NPART_ * TQ_ * D_];  // unnormalized partial outputs
__device__ float g_pm[NPART_ * TQ_];       // running max per (part, query)
__device__ float g_pl[NPART_ * TQ_];       // running sum-exp per (part, query)

// ---- packed f32x2 helpers (Blackwell) ----
__device__ __forceinline__ u64 fma2(u64 a, u64 b, u64 c) {
    u64 d; asm("fma.rn.f32x2 %0, %1, %2, %3;" : "=l"(d) : "l"(a), "l"(b), "l"(c));
    return d;
}
__device__ __forceinline__ u64 mul2(u64 a, u64 b) {
    u64 d; asm("mul.rn.f32x2 %0, %1, %2;" : "=l"(d) : "l"(a), "l"(b));
    return d;
}
__device__ __forceinline__ u64 pack2(float lo, float hi) {
    u64 d; asm("mov.b64 %0, {%1, %2};" : "=l"(d) : "f"(lo), "f"(hi));
    return d;
}
__device__ __forceinline__ float2 unpack2(u64 a) {
    float lo, hi; asm("mov.b64 {%0, %1}, %2;" : "=f"(lo), "=f"(hi) : "l"(a));
    return make_float2(lo, hi);
}
// fp16 round-trip of two floats, result packed as f32x2
__device__ __forceinline__ u64 h16rt2(float a, float b) {
    __half2 h = __floats2half2_rn(a, b);
    float2 f = __half22float2(h);
    return pack2(f.x, f.y);
}
// u32 bits -> half2
__device__ __forceinline__ __half2 h2u(unsigned b) {
    return *reinterpret_cast<__half2*>(&b);
}

__device__ __forceinline__ float tern(float x, float th) {
    // ternary {-1,0,+1}: strictly outside [-th, th]
    return (fabsf(x) > th) ? copysignf(1.0f, x) : 0.0f;
}

// scalar reduce-scatter of 8 query-dots over 8 d-octant lanes (3 rounds)
__device__ __forceinline__ float reduce_scatter8(const float* s, bool b2, bool b1, bool b0) {
    const float r0 = __shfl_xor_sync(0xffffffffu, b2 ? s[0] : s[4], 4);
    const float r1 = __shfl_xor_sync(0xffffffffu, b2 ? s[1] : s[5], 4);
    const float r2 = __shfl_xor_sync(0xffffffffu, b2 ? s[2] : s[6], 4);
    const float r3 = __shfl_xor_sync(0xffffffffu, b2 ? s[3] : s[7], 4);
    const float A0 = (b2 ? s[4] : s[0]) + r0;
    const float A1 = (b2 ? s[5] : s[1]) + r1;
    const float A2 = (b2 ? s[6] : s[2]) + r2;
    const float A3 = (b2 ? s[7] : s[3]) + r3;
    const float r4 = __shfl_xor_sync(0xffffffffu, b1 ? A0 : A2, 2);
    const float r5 = __shfl_xor_sync(0xffffffffu, b1 ? A1 : A3, 2);
    const float C0 = (b1 ? A2 : A0) + r4;
    const float C1 = (b1 ? A3 : A1) + r5;
    const float r6 = __shfl_xor_sync(0xffffffffu, b0 ? C0 : C1, 1);
    return (b0 ? C1 : C0) + r6;
}

__global__ __launch_bounds__(256, 2)
void attn_split_kernel(const float* __restrict__ q,
                       const float* __restrict__ k,
                       const float* __restrict__ v,
                       const float* __restrict__ logth)
{
    // q stored as fp16 (q * scale * thresh), blocked per (query, d-octant):
    // slot [j][a] holds the 16 halves of query j's 4 d-chunks for octant a,
    // padded to 24 halves (48B) so the 8-lane LDS.128 pattern is conflict-free.
    __shared__ __align__(16) __half q_h[TQ_][8][24];
    // probs, DUPLICATED as (p,p) u64 pairs, double-buffered for the 1-tile
    // software pipeline: [buf][warp][query][row]
    __shared__ __align__(16) u64 p_w2[2][8][TQ_][4];
    __shared__ float m_sm[8][TQ_];                    // epilogue: per-warp m
    __shared__ float l_sm[8][TQ_];                    // epilogue: per-warp l
    __shared__ __align__(16) float red_sm[8][D_];     // epilogue cross-warp reduce

    const int bid   = blockIdx.x;
    const int bh    = bid >> 3;              // (b*H + h)
    const int split = bid & (NSPLIT_ - 1);
    const int h     = bh & (H_ - 1);
    const int t     = threadIdx.x;
    const int w     = t >> 5;                // warp id
    const int lane  = t & 31;
    const int ar    = t >> 3;                // dot row within tile (0..31): 4w + rr
    const int adq   = t & 7;                 // d-octant AND assigned query
    const int rr    = lane >> 3;             // row-within-warp (0..3)

    // softplus (numerically stable, matches jax.nn.softplus)
    const float lt = logth[h];
    const float th = fmaxf(lt, 0.0f) + log1pf(expf(-fabsf(lt)));
    const float qmul = th * 0.08838834764831845f;   // thresh / sqrt(128)

    const float* qb = q + (size_t)bh * (TQ_ * D_);
    const float* kb = k + (size_t)bh * (KV_ * D_) + (size_t)split * (KVS_ * D_);
    const float* vb = v + (size_t)bh * (KV_ * D_) + (size_t)split * (KVS_ * D_);

    // load q scaled by thresh*scale into blocked fp16 layout
    for (int idx = t; idx < TQ_ * D_; idx += 256) {
        const int j = idx >> 7;
        const int d = idx & 127;
        const int i = d >> 5;          // d-chunk 0..3
        const int r = d & 31;
        const int a = r >> 2;          // octant 0..7
        const int e = r & 3;           // element in chunk
        q_h[j][a][i * 4 + e] = __float2half_rn(qb[idx] * qmul);
    }
    __syncthreads();

    // packed output accumulators (this warp's rows only; merged in epilogue)
    u64 o01[TQ_], o23[TQ_];
#pragma unroll
    for (int j = 0; j < TQ_; j++) { o01[j] = 0ULL; o23[j] = 0ULL; }
    float m_run = -INFINITY, l_run = 0.0f;
    float alpha_prev;   // alpha(t-1), carried across the pipeline

    const bool b2 = (adq & 4) != 0;
    const bool b1 = (adq & 2) != 0;
    const bool b0 = (adq & 1) != 0;

    const int brow = w << 2;        // phase B: rows w*4..w*4+3 within tile
    const int bd   = lane << 2;     // output column base

    const uint4* qslot = reinterpret_cast<const uint4*>(&q_h[0][adq][0]);
    // &q_h[j][adq][0] - &q_h[0][adq][0] = j*384 B = j*24 uint4s

    // K registers for this thread's row slice (tile 0)
    float4 kk[4];
    {
        const float* kp = kb + ar * D_ + adq * 4;
#pragma unroll
        for (int i = 0; i < 4; i++) kk[i] = *(const float4*)(kp + i * 32);
    }
    // V registers for warp's rows (tile 0)
    float4 vv[4];
    {
        const float* vp = vb + (size_t)brow * D_ + bd;
#pragma unroll
        for (int i2 = 0; i2 < 4; i2++) vv[i2] = *(const float4*)(vp + i2 * D_);
    }

    // ================= prologue: tile 0 dot + softmax (no phase B yet) ======
    {
        __half2 Eh[8];
#pragma unroll
        for (int i = 0; i < 4; i++) {
            Eh[2*i]   = __floats2half2_rn(tern(kk[i].x, th), tern(kk[i].y, th));
            Eh[2*i+1] = __floats2half2_rn(tern(kk[i].z, th), tern(kk[i].w, th));
        }
        float s[TQ_];
#pragma unroll
        for (int j = 0; j < TQ_; j++) {
            const uint4 wa = qslot[j * 24];
            const uint4 wb = qslot[j * 24 + 1];
            __half2 acc0 = __hmul2(h2u(wa.x), Eh[0]);
            __half2 acc1 = __hmul2(h2u(wa.y), Eh[1]);
            acc0 = __hfma2(h2u(wa.z), Eh[2], acc0);
            acc1 = __hfma2(h2u(wa.w), Eh[3], acc1);
            acc0 = __hfma2(h2u(wb.x), Eh[4], acc0);
            acc1 = __hfma2(h2u(wb.y), Eh[5], acc1);
            acc0 = __hfma2(h2u(wb.z), Eh[6], acc0);
            acc1 = __hfma2(h2u(wb.w), Eh[7], acc1);
            const float2 f0 = __half22float2(acc0);
            const float2 f1 = __half22float2(acc1);
            s[j] = (f0.x + f0.y) + (f1.x + f1.y);
        }
        // prefetch kk(1)
        {
            const float* kp = kb + (size_t)(TS_ + ar) * D_ + adq * 4;
#pragma unroll
            for (int i = 0; i < 4; i++) kk[i] = *(const float4*)(kp + i * 32);
        }
        const float own = reduce_scatter8(s, b2, b1, b0);
        float mt = own;
        mt = fmaxf(mt, __shfl_xor_sync(0xffffffffu, mt, 8));
        mt = fmaxf(mt, __shfl_xor_sync(0xffffffffu, mt, 16));
        const float m_new = fmaxf(m_run, mt);
        alpha_prev = __expf(m_run - m_new);   // == 0 for tile 0
        const float p = __expf(own - m_new);
        float ps = p;
        ps += __shfl_xor_sync(0xffffffffu, ps, 8);
        ps += __shfl_xor_sync(0xffffffffu, ps, 16);
        l_run = l_run * alpha_prev + ps;
        m_run = m_new;
        p_w2[0][w][adq][rr] = pack2(p, p);
        __syncwarp();
    }

    // ================= pipelined main loop: tiles 1..NTILES-1 ==============
#pragma unroll 1
    for (int tile = 1; tile < NTILES_; tile++) {
        // ---- ① dot(tile): tern + HFMA2 (kk dead after tern) ----
        __half2 Eh[8];
#pragma unroll
        for (int i = 0; i < 4; i++) {
            Eh[2*i]   = __floats2half2_rn(tern(kk[i].x, th), tern(kk[i].y, th));
            Eh[2*i+1] = __floats2half2_rn(tern(kk[i].z, th), tern(kk[i].w, th));
        }
        float s[TQ_];
#pragma unroll
        for (int j = 0; j < TQ_; j++) {
            const uint4 wa = qslot[j * 24];
            const uint4 wb = qslot[j * 24 + 1];
            __half2 acc0 = __hmul2(h2u(wa.x), Eh[0]);
            __half2 acc1 = __hmul2(h2u(wa.y), Eh[1]);
            acc0 = __hfma2(h2u(wa.z), Eh[2], acc0);
            acc1 = __hfma2(h2u(wa.w), Eh[3], acc1);
            acc0 = __hfma2(h2u(wb.x), Eh[4], acc0);
            acc1 = __hfma2(h2u(wb.y), Eh[5], acc1);
            acc0 = __hfma2(h2u(wb.z), Eh[6], acc0);
            acc1 = __hfma2(h2u(wb.w), Eh[7], acc1);
            const float2 f0 = __half22float2(acc0);
            const float2 f1 = __half22float2(acc1);
            s[j] = (f0.x + f0.y) + (f1.x + f1.y);
        }

        // ---- ② prefetch kk(tile+1) ----
        if (tile + 1 < NTILES_) {
            const float* kp = kb + (size_t)((tile + 1) * TS_ + ar) * D_ + adq * 4;
#pragma unroll
            for (int i = 0; i < 4; i++) kk[i] = *(const float4*)(kp + i * 32);
        }

        // ---- ③ phase B(tile-1): rescale + P·V (vv = V(tile-1)) ----
        {
            if (!__all_sync(0xffffffffu, alpha_prev == 1.0f)) {
#pragma unroll
                for (int j = 0; j < TQ_; j++) {
                    const float a = __shfl_sync(0xffffffffu, alpha_prev, j, 8);
                    const u64 A2v = pack2(a, a);
                    o01[j] = mul2(o01[j], A2v);
                    o23[j] = mul2(o23[j], A2v);
                }
            }
            u64 V01[4], V23[4];
#pragma unroll
            for (int i2 = 0; i2 < 4; i2++) {
                V01[i2] = h16rt2(vv[i2].x, vv[i2].y);   // exact fp16 round-trip
                V23[i2] = h16rt2(vv[i2].z, vv[i2].w);
            }
            const u64* pj = &p_w2[(tile - 1) & 1][w][0][0];
#pragma unroll
            for (int j = 0; j < TQ_; j++) {
                const ulonglong2 pa = *(const ulonglong2*)(pj + j * 4);
                const ulonglong2 pb = *(const ulonglong2*)(pj + j * 4 + 2);
                u64 x01 = o01[j], x23 = o23[j];
                x01 = fma2(pa.x, V01[0], x01); x23 = fma2(pa.x, V23[0], x23);
                x01 = fma2(pa.y, V01[1], x01); x23 = fma2(pa.y, V23[1], x23);
                x01 = fma2(pb.x, V01[2], x01); x23 = fma2(pb.x, V23[2], x23);
                x01 = fma2(pb.y, V01[3], x01); x23 = fma2(pb.y, V23[3], x23);
                o01[j] = x01; o23[j] = x23;
            }
        }

        // ---- ④ load V(tile) (vv free; used at ③ of tile+1) ----
        {
            const float* vp = vb + (size_t)(tile * TS_ + brow) * D_ + bd;
#pragma unroll
            for (int i2 = 0; i2 < 4; i2++) vv[i2] = *(const float4*)(vp + i2 * D_);
        }

        // ---- ⑤ reduce-scatter + softmax(tile) -> p buffer, alpha_prev ----
        {
            const float own = reduce_scatter8(s, b2, b1, b0);
            float mt = own;
            mt = fmaxf(mt, __shfl_xor_sync(0xffffffffu, mt, 8));
            mt = fmaxf(mt, __shfl_xor_sync(0xffffffffu, mt, 16));
            const float m_new = fmaxf(m_run, mt);
            const float alpha = __expf(m_run - m_new);
            const float p = __expf(own - m_new);
            float ps = p;
            ps += __shfl_xor_sync(0xffffffffu, ps, 8);
            ps += __shfl_xor_sync(0xffffffffu, ps, 16);
            l_run = l_run * alpha + ps;
            m_run = m_new;
            alpha_prev = alpha;
            p_w2[tile & 1][w][adq][rr] = pack2(p, p);
        }
        __syncwarp();
    }

    // ================= drain: phase B(NTILES-1) =============================
    {
        if (!__all_sync(0xffffffffu, alpha_prev == 1.0f)) {
#pragma unroll
            for (int j = 0; j < TQ_; j++) {
                const float a = __shfl_sync(0xffffffffu, alpha_prev, j, 8);
                const u64 A2v = pack2(a, a);
                o01[j] = mul2(o01[j], A2v);
                o23[j] = mul2(o23[j], A2v);
            }
        }
        u64 V01[4], V23[4];
#pragma unroll
        for (int i2 = 0; i2 < 4; i2++) {
            V01[i2] = h16rt2(vv[i2].x, vv[i2].y);
            V23[i2] = h16rt2(vv[i2].z, vv[i2].w);
        }
        const u64* pj = &p_w2[(NTILES_ - 1) & 1][w][0][0];
#pragma unroll
        for (int j = 0; j < TQ_; j++) {
            const ulonglong2 pa = *(const ulonglong2*)(pj + j * 4);
            const ulonglong2 pb = *(const ulonglong2*)(pj + j * 4 + 2);
            u64 x01 = o01[j], x23 = o23[j];
            x01 = fma2(pa.x, V01[0], x01); x23 = fma2(pa.x, V23[0], x23);
            x01 = fma2(pa.y, V01[1], x01); x23 = fma2(pa.y, V23[1], x23);
            x01 = fma2(pb.x, V01[2], x01); x23 = fma2(pb.x, V23[2], x23);
            x01 = fma2(pb.y, V01[3], x01); x23 = fma2(pb.y, V23[3], x23);
            o01[j] = x01; o23[j] = x23;
        }
    }

    // ---- epilogue: merge 8 per-warp (m,l,O) by log-sum-exp, write partial ----
    if (rr == 0) { m_sm[w][adq] = m_run; l_sm[w][adq] = l_run; }
    __syncthreads();

    float sc[TQ_];
#pragma unroll
    for (int j = 0; j < TQ_; j++) {
        float M = m_sm[0][j];
#pragma unroll
        for (int w2 = 1; w2 < 8; w2++) M = fmaxf(M, m_sm[w2][j]);
        sc[j] = __expf(m_sm[w][j] - M);   // this warp's rescale to CTA max
    }
    {
        const size_t pbase = (size_t)bid * (TQ_ * D_);
#pragma unroll 1
        for (int j = 0; j < TQ_; j++) {
            __syncthreads();   // previous iteration's reads done
            const u64 S2 = pack2(sc[j], sc[j]);
            const float2 a01 = unpack2(mul2(o01[j], S2));
            const float2 a23 = unpack2(mul2(o23[j], S2));
            *(float4*)&red_sm[w][bd] = make_float4(a01.x, a01.y, a23.x, a23.y);
            __syncthreads();
            if (t < D_) {
                float acc = red_sm[0][t];
#pragma unroll
                for (int w2 = 1; w2 < 8; w2++) acc += red_sm[w2][t];
                g_po[pbase + j * D_ + t] = acc;
            }
        }
        if (t < TQ_) {   // thread t == query j
            float M = m_sm[0][t];
#pragma unroll
            for (int w2 = 1; w2 < 8; w2++) M = fmaxf(M, m_sm[w2][t]);
            float L = 0.0f;
#pragma unroll
            for (int w2 = 0; w2 < 8; w2++)
                L = fmaf(__expf(m_sm[w2][t] - M), l_sm[w2][t], L);
            g_pm[bid * TQ_ + t] = M;
            g_pl[bid * TQ_ + t] = L;
        }
    }
}

__global__ __launch_bounds__(256)
void combine_kernel(float* __restrict__ out)
{
    const int bh = blockIdx.x;          // 0..255
    const int t  = threadIdx.x;
    const int j  = t >> 5;              // query
    const int d4 = (t & 31) << 2;       // column base

    float m[NSPLIT_];
    float M = -INFINITY;
#pragma unroll
    for (int i = 0; i < NSPLIT_; i++) {
        m[i] = g_pm[(bh * NSPLIT_ + i) * TQ_ + j];
        M = fmaxf(M, m[i]);
    }
    float W = 0.0f;
    float ax = 0.f, ay = 0.f, az = 0.f, aw = 0.f;
#pragma unroll
    for (int i = 0; i < NSPLIT_; i++) {
        const float wgt = __expf(m[i] - M);
        W = fmaf(wgt, g_pl[(bh * NSPLIT_ + i) * TQ_ + j], W);
        const float4 oi = *(const float4*)&g_po[((size_t)(bh * NSPLIT_ + i) * TQ_ + j) * D_ + d4];
        ax = fmaf(wgt, oi.x, ax);
        ay = fmaf(wgt, oi.y, ay);
        az = fmaf(wgt, oi.z, az);
        aw = fmaf(wgt, oi.w, aw);
    }
    const float inv = 1.0f / W;
    float4 r = make_float4(ax * inv, ay * inv, az * inv, aw * inv);
    *(float4*)&out[(size_t)bh * (TQ_ * D_) + j * D_ + d4] = r;
}

// diagnostic: pads launch count so ncu (-s 5 -c 1, observed +2 offset)
// lands on attn_split_kernel (profiled slot = our 4th launch)
__global__ void nop_kernel() {}

extern "C" void kernel_launch(void* const* d_in, const int* in_sizes, int n_in,
                              void* d_out, int out_size)
{
    const float* q    = (const float*)d_in[0];
    const float* k    = (const float*)d_in[1];
    const float* v    = (const float*)d_in[2];
    const float* logt = (const float*)d_in[3];
    float* out = (float*)d_out;

    nop_kernel<<<1, 32>>>();
    nop_kernel<<<1, 32>>>();
    nop_kernel<<<1, 32>>>();
    attn_split_kernel<<<NPART_, 256>>>(q, k, v, logt);
    combine_kernel<<<B_ * H_, 256>>>(out);
}

// round 17
// speedup vs baseline: 1.1506x; 1.1506x over previous
#include <cuda_runtime.h>
#include <cuda_fp16.h>
#include <math.h>

// Problem dims (fixed)
#define B_      8
#define H_      32
#define TQ_     8
#define KV_     4096
#define D_      128

// Split-KV config
#define NSPLIT_ 8
#define KVS_    (KV_ / NSPLIT_)   // 512 rows per split
#define TS_     32                // KV rows per tile
#define NTILES_ (KVS_ / TS_)      // 16
#define NPART_  (B_ * H_ * NSPLIT_) // 2048

typedef unsigned long long u64;

// Scratch for split partials (device globals: allocation-free)
__device__ float g_po[NPART_ * TQ_ * D_];  // unnormalized partial outputs
__device__ float g_pm[NPART_ * TQ_];       // running max per (part, query)
__device__ float g_pl[NPART_ * TQ_];       // running sum-exp per (part, query)

// ---- packed f32x2 helpers (Blackwell) ----
__device__ __forceinline__ u64 fma2(u64 a, u64 b, u64 c) {
    u64 d; asm("fma.rn.f32x2 %0, %1, %2, %3;" : "=l"(d) : "l"(a), "l"(b), "l"(c));
    return d;
}
__device__ __forceinline__ u64 mul2(u64 a, u64 b) {
    u64 d; asm("mul.rn.f32x2 %0, %1, %2;" : "=l"(d) : "l"(a), "l"(b));
    return d;
}
__device__ __forceinline__ u64 pack2(float lo, float hi) {
    u64 d; asm("mov.b64 %0, {%1, %2};" : "=l"(d) : "f"(lo), "f"(hi));
    return d;
}
__device__ __forceinline__ float2 unpack2(u64 a) {
    float lo, hi; asm("mov.b64 {%0, %1}, %2;" : "=f"(lo), "=f"(hi) : "l"(a));
    return make_float2(lo, hi);
}
// fp16 round-trip of two floats, result packed as f32x2
__device__ __forceinline__ u64 h16rt2(float a, float b) {
    __half2 h = __floats2half2_rn(a, b);
    float2 f = __half22float2(h);
    return pack2(f.x, f.y);
}
// u32 bits -> half2
__device__ __forceinline__ __half2 h2u(unsigned b) {
    return *reinterpret_cast<__half2*>(&b);
}

__device__ __forceinline__ float tern(float x, float th) {
    // ternary {-1,0,+1}: strictly outside [-th, th]
    return (fabsf(x) > th) ? copysignf(1.0f, x) : 0.0f;
}

// scalar reduce-scatter of 8 query-dots over 8 d-octant lanes (3 rounds)
__device__ __forceinline__ float reduce_scatter8(const float* s, bool b2, bool b1, bool b0) {
    const float r0 = __shfl_xor_sync(0xffffffffu, b2 ? s[0] : s[4], 4);
    const float r1 = __shfl_xor_sync(0xffffffffu, b2 ? s[1] : s[5], 4);
    const float r2 = __shfl_xor_sync(0xffffffffu, b2 ? s[2] : s[6], 4);
    const float r3 = __shfl_xor_sync(0xffffffffu, b2 ? s[3] : s[7], 4);
    const float A0 = (b2 ? s[4] : s[0]) + r0;
    const float A1 = (b2 ? s[5] : s[1]) + r1;
    const float A2 = (b2 ? s[6] : s[2]) + r2;
    const float A3 = (b2 ? s[7] : s[3]) + r3;
    const float r4 = __shfl_xor_sync(0xffffffffu, b1 ? A0 : A2, 2);
    const float r5 = __shfl_xor_sync(0xffffffffu, b1 ? A1 : A3, 2);
    const float C0 = (b1 ? A2 : A0) + r4;
    const float C1 = (b1 ? A3 : A1) + r5;
    const float r6 = __shfl_xor_sync(0xffffffffu, b0 ? C0 : C1, 1);
    return (b0 ? C1 : C0) + r6;
}

__global__ __launch_bounds__(256, 2)
void attn_split_kernel(const float* __restrict__ q,
                       const float* __restrict__ k,
                       const float* __restrict__ v,
                       const float* __restrict__ logth)
{
    // q stored as fp16 (q * scale * thresh), blocked per (query, d-octant):
    // slot [j][a] holds the 16 halves of query j's 4 d-chunks for octant a,
    // padded to 24 halves (48B) so the 8-lane LDS.128 pattern is conflict-free.
    __shared__ __align__(16) __half q_h[TQ_][8][24];
    __shared__ __align__(16) float p_w[8][TQ_][4];    // warp-private probs [w][j][rr]
    __shared__ float m_sm[8][TQ_];                    // epilogue: per-warp m
    __shared__ float l_sm[8][TQ_];                    // epilogue: per-warp l
    __shared__ __align__(16) float red_sm[8][TQ_ * D_]; // epilogue bulk reduce (32KB)

    const int bid   = blockIdx.x;
    const int bh    = bid >> 3;              // (b*H + h)
    const int split = bid & (NSPLIT_ - 1);
    const int h     = bh & (H_ - 1);
    const int t     = threadIdx.x;
    const int w     = t >> 5;                // warp id
    const int lane  = t & 31;
    const int ar    = t >> 3;                // dot row within tile (0..31): 4w + rr
    const int adq   = t & 7;                 // d-octant AND assigned query
    const int rr    = lane >> 3;             // row-within-warp (0..3)

    // softplus (numerically stable, matches jax.nn.softplus)
    const float lt = logth[h];
    const float th = fmaxf(lt, 0.0f) + log1pf(expf(-fabsf(lt)));
    const float qmul = th * 0.08838834764831845f;   // thresh / sqrt(128)

    const float* qb = q + (size_t)bh * (TQ_ * D_);
    const float* kb = k + (size_t)bh * (KV_ * D_) + (size_t)split * (KVS_ * D_);
    const float* vb = v + (size_t)bh * (KV_ * D_) + (size_t)split * (KVS_ * D_);

    // load q scaled by thresh*scale into blocked fp16 layout
    for (int idx = t; idx < TQ_ * D_; idx += 256) {
        const int j = idx >> 7;
        const int d = idx & 127;
        const int i = d >> 5;          // d-chunk 0..3
        const int r = d & 31;
        const int a = r >> 2;          // octant 0..7
        const int e = r & 3;           // element in chunk
        q_h[j][a][i * 4 + e] = __float2half_rn(qb[idx] * qmul);
    }
    __syncthreads();

    // packed output accumulators (this warp's rows only; merged in epilogue)
    u64 o01[TQ_], o23[TQ_];
#pragma unroll
    for (int j = 0; j < TQ_; j++) { o01[j] = 0ULL; o23[j] = 0ULL; }
    float m_run = -INFINITY, l_run = 0.0f;

    const bool b2 = (adq & 4) != 0;
    const bool b1 = (adq & 2) != 0;
    const bool b0 = (adq & 1) != 0;

    // K registers for this thread's row slice
    float4 kk[4];
    {
        const float* kp = kb + ar * D_ + adq * 4;
#pragma unroll
        for (int i = 0; i < 4; i++) kk[i] = *(const float4*)(kp + i * 32);
    }

    const int brow = w << 2;        // phase B: rows w*4..w*4+3 within tile
    const int bd   = lane << 2;     // output column base

    const uint4* qslot = reinterpret_cast<const uint4*>(&q_h[0][adq][0]);
    // &q_h[j][adq][0] - &q_h[0][adq][0] = j * 8 * 24 halves = j*384 B = j*24 uint4s

#pragma unroll 1
    for (int tile = 0; tile < NTILES_; tile++) {
        // ---- prefetch V for this tile (used in phase B) ----
        float4 vv[4];
        {
            const float* vp = vb + (size_t)(tile * TS_ + brow) * D_ + bd;
#pragma unroll
            for (int i2 = 0; i2 < 4; i2++) vv[i2] = *(const float4*)(vp + i2 * D_);
        }

        // ---- ternary dequant as half2 (EXACT for {-1,0,+1}); kk dead after ----
        __half2 Eh[8];
#pragma unroll
        for (int i = 0; i < 4; i++) {
            Eh[2*i]   = __floats2half2_rn(tern(kk[i].x, th), tern(kk[i].y, th));
            Eh[2*i+1] = __floats2half2_rn(tern(kk[i].z, th), tern(kk[i].w, th));
        }

        // ---- dot in fp16: products q*e are EXACT (e in {-1,0,1}); only adds
        //      round. Two independent 4-deep chains per query bound the error.
        float s[TQ_];
#pragma unroll
        for (int j = 0; j < TQ_; j++) {
            const uint4 wa = qslot[j * 24];      // halves 0..7  (chunks 0,1)
            const uint4 wb = qslot[j * 24 + 1];  // halves 8..15 (chunks 2,3)
            __half2 acc0 = __hmul2(h2u(wa.x), Eh[0]);
            __half2 acc1 = __hmul2(h2u(wa.y), Eh[1]);
            acc0 = __hfma2(h2u(wa.z), Eh[2], acc0);
            acc1 = __hfma2(h2u(wa.w), Eh[3], acc1);
            acc0 = __hfma2(h2u(wb.x), Eh[4], acc0);
            acc1 = __hfma2(h2u(wb.y), Eh[5], acc1);
            acc0 = __hfma2(h2u(wb.z), Eh[6], acc0);
            acc1 = __hfma2(h2u(wb.w), Eh[7], acc1);
            const float2 f0 = __half22float2(acc0);
            const float2 f1 = __half22float2(acc1);
            s[j] = (f0.x + f0.y) + (f1.x + f1.y);
        }

        // ---- prefetch next tile's K (kk dead now; hides DRAM latency) ----
        if (tile + 1 < NTILES_) {
            const float* kp = kb + (size_t)((tile + 1) * TS_ + ar) * D_ + adq * 4;
#pragma unroll
            for (int i = 0; i < 4; i++) kk[i] = *(const float4*)(kp + i * 32);
        }

        // ---- scalar reduce-scatter: lane adq gets query adq ----
        const float own = reduce_scatter8(s, b2, b1, b0);

        // ---- per-warp online softmax over its 4 rows, query adq per lane ----
        float alpha;
        {
            float mt = own;
            mt = fmaxf(mt, __shfl_xor_sync(0xffffffffu, mt, 8));
            mt = fmaxf(mt, __shfl_xor_sync(0xffffffffu, mt, 16));
            const float m_new = fmaxf(m_run, mt);
            alpha = __expf(m_run - m_new);  // 0 on first tile
            const float p = __expf(own - m_new);
            float ps = p;
            ps += __shfl_xor_sync(0xffffffffu, ps, 8);
            ps += __shfl_xor_sync(0xffffffffu, ps, 16);
            l_run = l_run * alpha + ps;
            m_run = m_new;
            p_w[w][adq][rr] = p;
        }
        __syncwarp();

        // ---- rescale (skipped when warp-uniformly alpha == 1) ----
        if (!__all_sync(0xffffffffu, alpha == 1.0f)) {
#pragma unroll
            for (int j = 0; j < TQ_; j++) {
                const float a = __shfl_sync(0xffffffffu, alpha, j, 8);
                const u64 A2v = pack2(a, a);
                o01[j] = mul2(o01[j], A2v);
                o23[j] = mul2(o23[j], A2v);
            }
        }

        // ---- phase B: P·V over this warp's 4 rows ----
        u64 V01[4], V23[4];
#pragma unroll
        for (int i2 = 0; i2 < 4; i2++) {
            V01[i2] = h16rt2(vv[i2].x, vv[i2].y);   // exact fp16 round-trip
            V23[i2] = h16rt2(vv[i2].z, vv[i2].w);
        }
#pragma unroll
        for (int j = 0; j < TQ_; j++) {
            const float4 p4 = *(const float4*)&p_w[w][j][0];
            u64 x01 = o01[j], x23 = o23[j];
            u64 P;
            P = pack2(p4.x, p4.x); x01 = fma2(P, V01[0], x01); x23 = fma2(P, V23[0], x23);
            P = pack2(p4.y, p4.y); x01 = fma2(P, V01[1], x01); x23 = fma2(P, V23[1], x23);
            P = pack2(p4.z, p4.z); x01 = fma2(P, V01[2], x01); x23 = fma2(P, V23[2], x23);
            P = pack2(p4.w, p4.w); x01 = fma2(P, V01[3], x01); x23 = fma2(P, V23[3], x23);
            o01[j] = x01; o23[j] = x23;
        }
        __syncwarp();   // protect p_w before next tile's overwrite
    }

    // ---- epilogue: single-sync bulk merge of 8 per-warp (m,l,O) ----
    if (rr == 0) { m_sm[w][adq] = m_run; l_sm[w][adq] = l_run; }
    __syncthreads();

    // scale this warp's partials to the CTA max and store ALL of them
#pragma unroll
    for (int j = 0; j < TQ_; j++) {
        float M = m_sm[0][j];
#pragma unroll
        for (int w2 = 1; w2 < 8; w2++) M = fmaxf(M, m_sm[w2][j]);
        const float scj = __expf(m_sm[w][j] - M);   // warp rescale to CTA max
        const u64 S2 = pack2(scj, scj);
        const float2 a01 = unpack2(mul2(o01[j], S2));
        const float2 a23 = unpack2(mul2(o23[j], S2));
        *(float4*)&red_sm[w][j * D_ + bd] = make_float4(a01.x, a01.y, a23.x, a23.y);
    }
    __syncthreads();

    // reduce 1024 outputs with 256 threads (4 columns each), write partial
    {
        const size_t pbase = (size_t)bid * (TQ_ * D_);
        const int jj = t >> 5;            // query
        const int cc = (t & 31) << 2;     // column base
        float4 acc = *(const float4*)&red_sm[0][jj * D_ + cc];
#pragma unroll
        for (int w2 = 1; w2 < 8; w2++) {
            const float4 r = *(const float4*)&red_sm[w2][jj * D_ + cc];
            acc.x += r.x; acc.y += r.y; acc.z += r.z; acc.w += r.w;
        }
        *(float4*)&g_po[pbase + jj * D_ + cc] = acc;

        if (t < TQ_) {   // thread t == query j
            float M = m_sm[0][t];
#pragma unroll
            for (int w2 = 1; w2 < 8; w2++) M = fmaxf(M, m_sm[w2][t]);
            float L = 0.0f;
#pragma unroll
            for (int w2 = 0; w2 < 8; w2++)
                L = fmaf(__expf(m_sm[w2][t] - M), l_sm[w2][t], L);
            g_pm[bid * TQ_ + t] = M;
            g_pl[bid * TQ_ + t] = L;
        }
    }
}

// one block per (bh, query) row; one thread per output column
__global__ __launch_bounds__(128)
void combine_kernel(float* __restrict__ out)
{
    const int bid = blockIdx.x;          // 0..2047
    const int bh  = bid >> 3;
    const int j   = bid & 7;
    const int d   = threadIdx.x;         // 0..127

    float m[NSPLIT_];
    float M = -INFINITY;
#pragma unroll
    for (int i = 0; i < NSPLIT_; i++) {
        m[i] = g_pm[(bh * NSPLIT_ + i) * TQ_ + j];
        M = fmaxf(M, m[i]);
    }
    float W = 0.0f;
    float acc = 0.0f;
#pragma unroll
    for (int i = 0; i < NSPLIT_; i++) {
        const float wgt = __expf(m[i] - M);
        W = fmaf(wgt, g_pl[(bh * NSPLIT_ + i) * TQ_ + j], W);
        acc = fmaf(wgt, g_po[((size_t)(bh * NSPLIT_ + i) * TQ_ + j) * D_ + d], acc);
    }
    out[((size_t)bh * TQ_ + j) * D_ + d] = acc / W;
}

extern "C" void kernel_launch(void* const* d_in, const int* in_sizes, int n_in,
                              void* d_out, int out_size)
{
    const float* q    = (const float*)d_in[0];
    const float* k    = (const float*)d_in[1];
    const float* v    = (const float*)d_in[2];
    const float* logt = (const float*)d_in[3];
    float* out = (float*)d_out;

    attn_split_kernel<<<NPART_, 256>>>(q, k, v, logt);
    combine_kernel<<<B_ * H_ * TQ_, 128>>>(out);
}